// round 2
// baseline (speedup 1.0000x reference)
#include <cuda_runtime.h>
#include <math.h>

#define Bb 32
#define Tt 64
#define Ss 256
#define Hh 512
#define Ee 256
#define Vv 32000
#define NHh 8
#define HDd 64
#define STEPS 63   // T-1

// ---------------- scratch (single __device__ buffer, no allocations) ----------
#define O_KH   0
#define O_VH   (O_KH  + Bb*Ss*Hh)
#define O_H0   (O_VH  + Bb*Ss*Hh)
#define O_H1   (O_H0  + Bb*Hh)
#define O_EMB  (O_H1  + Bb*Hh)
#define O_Q    (O_EMB + Bb*Hh)
#define O_CTXP (O_Q   + Bb*Hh)
#define O_CTX  (O_CTXP+ Bb*Hh)
#define O_GI0  (O_CTX + Bb*Hh)
#define O_GH0  (O_GI0 + Bb*3*Hh)
#define O_GI1  (O_GH0 + Bb*3*Hh)
#define O_GH1  (O_GI1 + Bb*3*Hh)
#define O_H0P  (O_GH1 + Bb*3*Hh)
#define O_COMB (O_H0P + Bb*Hh)
#define O_O1   (O_COMB+ STEPS*Bb*2*Hh)
#define O_TOTAL (O_O1 + STEPS*Bb*Hh)

__device__ float g_buf[O_TOTAL];

__device__ __forceinline__ float clip100(float v){ return fminf(fmaxf(v,-100.f),100.f); }
__device__ __forceinline__ float sigmoidf_(float x){ return 1.f/(1.f+expf(-x)); }

// ---------------- init & zero ------------------------------------------------
__global__ void init_kernel(const float* __restrict__ dec, float* h0, float* h1){
    int i = blockIdx.x*256 + threadIdx.x;
    if (i < Bb*Hh){
        float v = fminf(fmaxf(dec[i], -10.f), 10.f);
        h0[i] = v; h1[i] = v;
    }
}

__global__ void zero_kernel(float* __restrict__ out){
    int i = blockIdx.x*256 + threadIdx.x;
    if (i < Bb*Vv){
        int b = i / Vv, v = i % Vv;
        out[(size_t)b*Tt*Vv + v] = 0.f;
    }
}

// ---------------- big tiled SGEMM: C[M,N] = act(A[M,K] @ W[N,K]^T + bias) -----
// mode: 0 plain, 1 clip100, 2 relu, 3 clip100 + scatter into [B,T,V] at t+1
__global__ void gemm128_kernel(const float* __restrict__ A, const float* __restrict__ W,
                               const float* __restrict__ bias, float* __restrict__ C,
                               int M, int N, int K, int mode){
    __shared__ float As[8][128];
    __shared__ float Ws[8][128];
    const int tid = threadIdx.x;
    const int bm = blockIdx.y * 128;
    const int bn = blockIdx.x * 128;
    const int lrow = tid >> 1;          // 0..127
    const int lk4  = (tid & 1) * 4;     // 0 or 4
    const int tx = tid & 15, ty = tid >> 4;

    float acc[8][8];
    #pragma unroll
    for (int i=0;i<8;i++)
        #pragma unroll
        for (int j=0;j<8;j++) acc[i][j]=0.f;

    for (int kb = 0; kb < K; kb += 8){
        float4 av = make_float4(0.f,0.f,0.f,0.f);
        int ar = bm + lrow;
        if (ar < M) av = *(const float4*)(A + (size_t)ar*K + kb + lk4);
        As[lk4+0][lrow]=av.x; As[lk4+1][lrow]=av.y; As[lk4+2][lrow]=av.z; As[lk4+3][lrow]=av.w;
        float4 wv = *(const float4*)(W + (size_t)(bn+lrow)*K + kb + lk4);
        Ws[lk4+0][lrow]=wv.x; Ws[lk4+1][lrow]=wv.y; Ws[lk4+2][lrow]=wv.z; Ws[lk4+3][lrow]=wv.w;
        __syncthreads();
        #pragma unroll
        for (int k=0;k<8;k++){
            float4 a0 = *(const float4*)&As[k][ty*4];
            float4 a1 = *(const float4*)&As[k][64 + ty*4];
            float4 b0 = *(const float4*)&Ws[k][tx*4];
            float4 b1 = *(const float4*)&Ws[k][64 + tx*4];
            float am[8] = {a0.x,a0.y,a0.z,a0.w, a1.x,a1.y,a1.z,a1.w};
            float bm_[8]= {b0.x,b0.y,b0.z,b0.w, b1.x,b1.y,b1.z,b1.w};
            #pragma unroll
            for (int i=0;i<8;i++)
                #pragma unroll
                for (int j=0;j<8;j++)
                    acc[i][j] += am[i]*bm_[j];
        }
        __syncthreads();
    }

    #pragma unroll
    for (int i=0;i<8;i++){
        int gm = bm + (i<4 ? ty*4+i : 64 + ty*4 + (i-4));
        if (gm >= M) continue;
        #pragma unroll
        for (int j=0;j<8;j++){
            int gn = bn + (j<4 ? tx*4+j : 64 + tx*4 + (j-4));
            float v = acc[i][j] + bias[gn];
            if (mode==1 || mode==3) v = clip100(v);
            else if (mode==2)       v = fmaxf(v, 0.f);
            if (mode==3){
                int b = gm & 31, t = gm >> 5;    // row = t*B + b
                C[((size_t)b*Tt + t + 1)*Vv + gn] = v;
            } else {
                C[(size_t)gm*N + gn] = v;
            }
        }
    }
}

// ---------------- small-M GEMM (M=32): C[32,N] = act(A@W^T + bias) ------------
// gidx: optional row gather (row = gidx[m*gstride]); A2/K1: optional concat
__global__ void gemm_small_kernel(const float* __restrict__ A, const float* __restrict__ A2,
                                  int K1, const int* __restrict__ gidx, int gstride, int lda,
                                  const float* __restrict__ W, const float* __restrict__ bias,
                                  float* __restrict__ C, int N, int K, int mode){
    __shared__ float As[32][33];
    __shared__ float Ws[64][33];
    const int tid = threadIdx.x;
    const int nb = blockIdx.x * 64;
    const int tn = tid & 63, tg = tid >> 6;   // tg in 0..3, 8 m-rows each
    float acc[8];
    #pragma unroll
    for (int i=0;i<8;i++) acc[i]=0.f;

    for (int kb = 0; kb < K; kb += 32){
        for (int idx = tid; idx < 32*32; idx += 256){
            int m = idx >> 5, k = idx & 31;
            int gk = kb + k;
            int row = gidx ? gidx[m*gstride] : m;
            float v = (gk < K1) ? A[(size_t)row*lda + gk]
                                : A2[(size_t)row*lda + (gk - K1)];
            As[m][k] = v;
        }
        for (int idx = tid; idx < 64*32; idx += 256){
            int n = idx >> 5, k = idx & 31;
            Ws[n][k] = W[(size_t)(nb+n)*K + kb + k];
        }
        __syncthreads();
        #pragma unroll 8
        for (int k=0;k<32;k++){
            float w = Ws[tn][k];
            #pragma unroll
            for (int i=0;i<8;i++)
                acc[i] += As[tg*8+i][k] * w;
        }
        __syncthreads();
    }
    float bval = bias[nb+tn];
    #pragma unroll
    for (int i=0;i<8;i++){
        float v = acc[i] + bval;
        if (mode==1) v = clip100(v);
        C[(size_t)(tg*8+i)*N + nb + tn] = v;
    }
}

// ---------------- attention: one block per (b, head) --------------------------
__global__ void attn_kernel(const float* __restrict__ q, const float* __restrict__ Kh,
                            const float* __restrict__ Vh, const int* __restrict__ mask,
                            float* __restrict__ ctx){
    const int bh = blockIdx.x;
    const int b = bh >> 3, nh = bh & 7;
    const int tid = threadIdx.x;  // 256 = S
    __shared__ float qs[64];
    __shared__ float sc[256];
    __shared__ float red[256];
    __shared__ float psum[4][64];

    if (tid < 64) qs[tid] = q[b*Hh + nh*HDd + tid];
    __syncthreads();

    const float* kp = Kh + ((size_t)b*Ss + tid)*Hh + nh*HDd;
    float s = 0.f;
    #pragma unroll
    for (int d=0; d<64; d+=4){
        float4 kv = *(const float4*)(kp + d);
        s += qs[d]*kv.x + qs[d+1]*kv.y + qs[d+2]*kv.z + qs[d+3]*kv.w;
    }
    s *= 0.125f;
    if (mask[b*Ss + tid] == 0) s = -10000.f;

    red[tid] = s;
    __syncthreads();
    #pragma unroll
    for (int off=128; off>0; off>>=1){
        if (tid < off) red[tid] = fmaxf(red[tid], red[tid+off]);
        __syncthreads();
    }
    float mx = red[0];
    __syncthreads();

    float e = expf(s - mx);
    sc[tid] = e;
    red[tid] = e;
    __syncthreads();
    #pragma unroll
    for (int off=128; off>0; off>>=1){
        if (tid < off) red[tid] += red[tid+off];
        __syncthreads();
    }
    float inv = 1.f / red[0];
    __syncthreads();

    const int d = tid & 63, part = tid >> 6;
    const float* vp = Vh + (size_t)b*Ss*Hh + nh*HDd + d;
    float p = 0.f;
    #pragma unroll 4
    for (int ss = part*64; ss < part*64 + 64; ss++)
        p += sc[ss] * vp[(size_t)ss*Hh];
    psum[part][d] = p;
    __syncthreads();
    if (tid < 64){
        float r = (psum[0][tid]+psum[1][tid]+psum[2][tid]+psum[3][tid]) * inv;
        ctx[b*Hh + nh*HDd + tid] = r;
    }
}

// ---------------- GRU elementwise ---------------------------------------------
__global__ void gru_ew_kernel(const float* __restrict__ gi, const float* __restrict__ gh,
                              const float* __restrict__ hprev,
                              float* hpre, float* hclip, float* comb,
                              const float* __restrict__ ctx){
    int idx = blockIdx.x*256 + threadIdx.x;
    if (idx >= Bb*Hh) return;
    int b = idx >> 9, j = idx & 511;
    int base = b*3*Hh + j;
    float ir = gi[base], iz = gi[base+Hh], in_ = gi[base+2*Hh];
    float hr = gh[base], hz = gh[base+Hh], hn  = gh[base+2*Hh];
    float r = sigmoidf_(ir + hr);
    float z = sigmoidf_(iz + hz);
    float n = tanhf(in_ + r*hn);
    float h = (1.f - z)*n + z*hprev[idx];
    if (hpre)  hpre[idx] = h;
    hclip[idx] = fminf(fmaxf(h, -10.f), 10.f);
    if (comb){
        comb[b*2*Hh + j]       = h;            // pre-clip h1
        comb[b*2*Hh + Hh + j]  = ctx[idx];
    }
}

// ---------------- driver -------------------------------------------------------
extern "C" void kernel_launch(void* const* d_in, const int* in_sizes, int n_in,
                              void* d_out, int out_size){
    const int*   tgt   = (const int*)  d_in[0];
    const float* enc   = (const float*)d_in[1];
    const float* dec   = (const float*)d_in[2];
    const int*   mask  = (const int*)  d_in[3];
    const float* embt  = (const float*)d_in[4];
    const float* w_ep  = (const float*)d_in[5];
    const float* b_ep  = (const float*)d_in[6];
    const float* wq    = (const float*)d_in[7];
    const float* bq    = (const float*)d_in[8];
    const float* wk    = (const float*)d_in[9];
    const float* bk    = (const float*)d_in[10];
    const float* wv    = (const float*)d_in[11];
    const float* bv    = (const float*)d_in[12];
    const float* wo    = (const float*)d_in[13];
    const float* bo    = (const float*)d_in[14];
    const float* w_ih0 = (const float*)d_in[15];
    const float* w_hh0 = (const float*)d_in[16];
    const float* b_ih0 = (const float*)d_in[17];
    const float* b_hh0 = (const float*)d_in[18];
    const float* w_ih1 = (const float*)d_in[19];
    const float* w_hh1 = (const float*)d_in[20];
    const float* b_ih1 = (const float*)d_in[21];
    const float* b_hh1 = (const float*)d_in[22];
    const float* w_o1  = (const float*)d_in[23];
    const float* b_o1  = (const float*)d_in[24];
    const float* w_o2  = (const float*)d_in[25];
    const float* b_o2  = (const float*)d_in[26];
    float* out = (float*)d_out;

    float* buf = nullptr;
    cudaGetSymbolAddress((void**)&buf, g_buf);

    float* Kh   = buf + O_KH;
    float* Vh   = buf + O_VH;
    float* h0   = buf + O_H0;
    float* h1   = buf + O_H1;
    float* emb  = buf + O_EMB;
    float* q    = buf + O_Q;
    float* ctxp = buf + O_CTXP;
    float* ctx  = buf + O_CTX;
    float* gi0  = buf + O_GI0;
    float* gh0  = buf + O_GH0;
    float* gi1  = buf + O_GI1;
    float* gh1  = buf + O_GH1;
    float* h0p  = buf + O_H0P;
    float* comb = buf + O_COMB;
    float* o1   = buf + O_O1;

    // step-invariant K/V projections (Kh clipped, Vh plain)
    gemm128_kernel<<<dim3(Hh/128, (Bb*Ss)/128), 256>>>(enc, wk, bk, Kh, Bb*Ss, Hh, Hh, 1);
    gemm128_kernel<<<dim3(Hh/128, (Bb*Ss)/128), 256>>>(enc, wv, bv, Vh, Bb*Ss, Hh, Hh, 0);
    init_kernel<<<(Bb*Hh+255)/256, 256>>>(dec, h0, h1);
    zero_kernel<<<(Bb*Vv+255)/256, 256>>>(out);

    for (int t = 0; t < STEPS; t++){
        // emb = emb_table[tgt[:,t]] @ w_ep^T + b_ep
        gemm_small_kernel<<<Hh/64, 256>>>(embt, embt, Ee, tgt + t, Tt, Ee,
                                          w_ep, b_ep, emb, Hh, Ee, 0);
        // q = clip(h1 @ wq^T + bq)
        gemm_small_kernel<<<Hh/64, 256>>>(h1, h1, Hh, nullptr, 0, Hh,
                                          wq, bq, q, Hh, Hh, 1);
        attn_kernel<<<Bb*NHh, 256>>>(q, Kh, Vh, mask, ctxp);
        // ctx = clip(ctxp @ wo^T + bo)
        gemm_small_kernel<<<Hh/64, 256>>>(ctxp, ctxp, Hh, nullptr, 0, Hh,
                                          wo, bo, ctx, Hh, Hh, 1);
        // gi0 = [emb, ctx] @ w_ih0^T + b_ih0
        gemm_small_kernel<<<(3*Hh)/64, 256>>>(emb, ctx, Hh, nullptr, 0, Hh,
                                              w_ih0, b_ih0, gi0, 3*Hh, 2*Hh, 0);
        // gh0 = h0 @ w_hh0^T + b_hh0
        gemm_small_kernel<<<(3*Hh)/64, 256>>>(h0, h0, Hh, nullptr, 0, Hh,
                                              w_hh0, b_hh0, gh0, 3*Hh, Hh, 0);
        // gh1 = h1 @ w_hh1^T + b_hh1  (uses previous h1, before it's overwritten)
        gemm_small_kernel<<<(3*Hh)/64, 256>>>(h1, h1, Hh, nullptr, 0, Hh,
                                              w_hh1, b_hh1, gh1, 3*Hh, Hh, 0);
        // GRU0 elementwise -> h0p (pre-clip), h0 (clipped state)
        gru_ew_kernel<<<(Bb*Hh+255)/256, 256>>>(gi0, gh0, h0, h0p, h0, nullptr, nullptr);
        // gi1 = h0p @ w_ih1^T + b_ih1  (unclipped h0 feeds GRU1, per reference)
        gemm_small_kernel<<<(3*Hh)/64, 256>>>(h0p, h0p, Hh, nullptr, 0, Hh,
                                              w_ih1, b_ih1, gi1, 3*Hh, Hh, 0);
        // GRU1 elementwise -> comb[t] = [h1_pre, ctx], h1 (clipped state)
        gru_ew_kernel<<<(Bb*Hh+255)/256, 256>>>(gi1, gh1, h1, nullptr, h1,
                                                comb + (size_t)t*Bb*2*Hh, ctx);
    }

    // batched output MLP over all 63 steps
    gemm128_kernel<<<dim3(Hh/128, (STEPS*Bb+127)/128), 256>>>(
        comb, w_o1, b_o1, o1, STEPS*Bb, Hh, 2*Hh, 2);           // relu
    gemm128_kernel<<<dim3(Vv/128, (STEPS*Bb+127)/128), 256>>>(
        o1, w_o2, b_o2, out, STEPS*Bb, Vv, Hh, 3);              // clip + scatter
}

// round 4
// speedup vs baseline: 2.9087x; 2.9087x over previous
#include <cuda_runtime.h>
#include <math.h>

#define Bb 32
#define Tt 64
#define Ss 256
#define Hh 512
#define Ee 256
#define Vv 32000
#define NHh 8
#define STEPS 63
#define NBLK 148
#define NPHASE 6

// ---------------- scratch ----------------------------------------------------
#define O_KH   0
#define O_VH   (O_KH  + Bb*Ss*Hh)
#define O_H0   (O_VH  + Bb*Ss*Hh)
#define O_H1   (O_H0  + Bb*Hh)
#define O_H0P  (O_H1  + Bb*Hh)
#define O_EMB  (O_H0P + Bb*Hh)
#define O_CTXP (O_EMB + Bb*Hh)
#define O_CTX  (O_CTXP+ Bb*Hh)
#define O_GH0  (O_CTX + Bb*Hh)
#define O_GH1  (O_GH0 + Bb*3*Hh)
#define O_GI0  (O_GH1 + Bb*3*Hh)
#define O_GI1  (O_GI0 + Bb*3*Hh)
#define O_COMB (O_GI1 + Bb*3*Hh)
#define O_O1   (O_COMB + STEPS*Bb*2*Hh)
#define O_TOTAL (O_O1 + STEPS*Bb*Hh)

__device__ float g_buf[O_TOTAL];
__device__ unsigned g_task[STEPS*NPHASE];
__device__ unsigned g_cnt = 0;
__device__ unsigned g_gen = 0;

__device__ __forceinline__ float clip100(float v){ return fminf(fmaxf(v,-100.f),100.f); }
__device__ __forceinline__ float sigm(float x){ return 1.f/(1.f+expf(-x)); }

// ---------------- init & zero ------------------------------------------------
__global__ void init_kernel(const float* __restrict__ dec, float* h0, float* h1){
    int i = blockIdx.x*256 + threadIdx.x;
    if (i < Bb*Hh){
        float v = fminf(fmaxf(dec[i], -10.f), 10.f);
        h0[i] = v; h1[i] = v;
    }
}

__global__ void reset_kernel(){
    int i = blockIdx.x*256 + threadIdx.x;
    if (i < STEPS*NPHASE) g_task[i] = 0u;
    if (i == 0) { g_cnt = 0u; g_gen = 0u; }
}

__global__ void zero_kernel(float* __restrict__ out){
    int i = blockIdx.x*256 + threadIdx.x;
    if (i < Bb*Vv){
        int b = i / Vv, v = i % Vv;
        out[(size_t)b*Tt*Vv + v] = 0.f;
    }
}

// ---------------- big tiled SGEMM (for KV proj + output MLP) ------------------
// mode: 0 plain, 1 clip100, 2 relu, 3 clip100 + scatter into [B,T,V] at t+1
__global__ void gemm128_kernel(const float* __restrict__ A, const float* __restrict__ W,
                               const float* __restrict__ bias, float* __restrict__ C,
                               int M, int N, int K, int mode){
    __shared__ float As[8][128];
    __shared__ float Ws[8][128];
    const int tid = threadIdx.x;
    const int bm = blockIdx.y * 128;
    const int bn = blockIdx.x * 128;
    const int lrow = tid >> 1;
    const int lk4  = (tid & 1) * 4;
    const int tx = tid & 15, ty = tid >> 4;

    float acc[8][8];
    #pragma unroll
    for (int i=0;i<8;i++)
        #pragma unroll
        for (int j=0;j<8;j++) acc[i][j]=0.f;

    for (int kb = 0; kb < K; kb += 8){
        float4 av = make_float4(0.f,0.f,0.f,0.f);
        int ar = bm + lrow;
        if (ar < M) av = *(const float4*)(A + (size_t)ar*K + kb + lk4);
        As[lk4+0][lrow]=av.x; As[lk4+1][lrow]=av.y; As[lk4+2][lrow]=av.z; As[lk4+3][lrow]=av.w;
        float4 wv = *(const float4*)(W + (size_t)(bn+lrow)*K + kb + lk4);
        Ws[lk4+0][lrow]=wv.x; Ws[lk4+1][lrow]=wv.y; Ws[lk4+2][lrow]=wv.z; Ws[lk4+3][lrow]=wv.w;
        __syncthreads();
        #pragma unroll
        for (int k=0;k<8;k++){
            float4 a0 = *(const float4*)&As[k][ty*4];
            float4 a1 = *(const float4*)&As[k][64 + ty*4];
            float4 b0 = *(const float4*)&Ws[k][tx*4];
            float4 b1 = *(const float4*)&Ws[k][64 + tx*4];
            float am[8] = {a0.x,a0.y,a0.z,a0.w, a1.x,a1.y,a1.z,a1.w};
            float bm_[8]= {b0.x,b0.y,b0.z,b0.w, b1.x,b1.y,b1.z,b1.w};
            #pragma unroll
            for (int i=0;i<8;i++)
                #pragma unroll
                for (int j=0;j<8;j++)
                    acc[i][j] += am[i]*bm_[j];
        }
        __syncthreads();
    }

    #pragma unroll
    for (int i=0;i<8;i++){
        int gm = bm + (i<4 ? ty*4+i : 64 + ty*4 + (i-4));
        if (gm >= M) continue;
        #pragma unroll
        for (int j=0;j<8;j++){
            int gn = bn + (j<4 ? tx*4+j : 64 + tx*4 + (j-4));
            float v = acc[i][j] + bias[gn];
            if (mode==1 || mode==3) v = clip100(v);
            else if (mode==2)       v = fmaxf(v, 0.f);
            if (mode==3){
                int b = gm & 31, t = gm >> 5;
                C[((size_t)b*Tt + t + 1)*Vv + gn] = v;
            } else {
                C[(size_t)gm*N + gn] = v;
            }
        }
    }
}

// ---------------- persistent decoder loop -------------------------------------
struct SmemG { float As[32*132]; float Ws[32*128]; };
struct SmemA { float hs[512]; float qs[64]; float sc[256]; float red[256]; float psum[4][64]; };
union SmemU { SmemG g; SmemA a; };

struct Params {
    const int*   tgt;  const int* mask;
    const float* embt; const float* w_ep; const float* b_ep;
    const float* wq;   const float* bq;
    const float* wo;   const float* bo;
    const float* w_ih0; const float* w_hh0; const float* b_ih0; const float* b_hh0;
    const float* w_ih1; const float* w_hh1; const float* b_ih1; const float* b_hh1;
    const float* Kh; const float* Vh;
    float *h0, *h1, *h0p, *emb, *ctxp, *ctx, *gh0, *gh1, *gi0, *gi1, *comb;
};

__device__ __forceinline__ void grid_bar(){
    __syncthreads();
    if (threadIdx.x == 0){
        __threadfence();
        unsigned gen = *((volatile unsigned*)&g_gen);
        if (atomicAdd(&g_cnt, 1u) == NBLK - 1){
            *((volatile unsigned*)&g_cnt) = 0u;
            __threadfence();
            *((volatile unsigned*)&g_gen) = gen + 1u;
        } else {
            while (*((volatile unsigned*)&g_gen) == gen) { __nanosleep(32); }
        }
    }
    __syncthreads();
}

// M=32 GEMM: lane = m (A row in registers), W broadcast from smem.
// AK: 0 plain (lda=512), 1 gather rows (embt, lda=256), 2 concat [emb|ctx]
template<int NW, int AK>
__device__ void gemm_task(SmemU* sm, int n0,
                          const float* __restrict__ A, const float* __restrict__ A2,
                          int K, const float* __restrict__ W, const float* __restrict__ bias,
                          float* __restrict__ C, int ldc, int act, const int* sRow)
{
    const int tid = threadIdx.x;
    const int lane = tid & 31;
    const int wp = tid >> 5;
    float acc[NW];
    #pragma unroll
    for (int i=0;i<NW;i++) acc[i]=0.f;

    for (int kb=0; kb<K; kb+=128){
        #pragma unroll
        for (int p=0;p<4;p++){
            int idx = tid + p*256;
            int r = idx >> 5, c4 = (idx & 31)*4;
            float4 v;
            if (AK==0) v = *(const float4*)(A + r*512 + kb + c4);
            else if (AK==1) v = *(const float4*)(A + sRow[r]*Ee + kb + c4);
            else { int kk = kb + c4;
                   v = (kk < 512) ? *(const float4*)(A + r*512 + kk)
                                  : *(const float4*)(A2 + r*512 + kk - 512); }
            *(float4*)&sm->g.As[r*132 + c4] = v;
        }
        const int nTask = NW*8;
        for (int idx = tid; idx < nTask*32; idx += 256){
            int n = idx >> 5, c4 = (idx & 31)*4;
            *(float4*)&sm->g.Ws[n*128 + c4] = *(const float4*)(W + (size_t)(n0+n)*K + kb + c4);
        }
        __syncthreads();
        #pragma unroll
        for (int kc=0; kc<128; kc+=32){
            float a[32];
            #pragma unroll
            for (int j=0;j<32;j+=4)
                *(float4*)&a[j] = *(const float4*)&sm->g.As[lane*132 + kc + j];
            #pragma unroll
            for (int nn=0;nn<NW;nn++){
                const float* wr = &sm->g.Ws[(wp*NW+nn)*128 + kc];
                float s0=0.f, s1=0.f;
                #pragma unroll
                for (int j=0;j<32;j+=8){
                    float4 w0 = *(const float4*)(wr + j);
                    float4 w1 = *(const float4*)(wr + j + 4);
                    s0 += a[j+0]*w0.x + a[j+1]*w0.y + a[j+2]*w0.z + a[j+3]*w0.w;
                    s1 += a[j+4]*w1.x + a[j+5]*w1.y + a[j+6]*w1.z + a[j+7]*w1.w;
                }
                acc[nn] += s0 + s1;
            }
        }
        __syncthreads();
    }
    #pragma unroll
    for (int nn=0;nn<NW;nn++){
        int n = n0 + wp*NW + nn;
        float v = acc[nn] + bias[n];
        if (act) v = clip100(v);
        C[lane*ldc + n] = v;
    }
}

// fused q-projection + attention for one (b, head)
__device__ void attn_task(SmemU* sm, const Params& P, int b, int h){
    const int tid = threadIdx.x;
    for (int i=tid; i<512; i+=256) sm->a.hs[i] = P.h1[b*Hh + i];
    __syncthreads();
    {
        int o = tid >> 2, part = tid & 3;
        const float* wr = P.wq + (size_t)(h*64 + o)*Hh + part*128;
        const float* hp = sm->a.hs + part*128;
        float s = 0.f;
        #pragma unroll
        for (int j=0;j<128;j+=4){
            float4 wv = *(const float4*)(wr + j);
            s += hp[j]*wv.x + hp[j+1]*wv.y + hp[j+2]*wv.z + hp[j+3]*wv.w;
        }
        s += __shfl_xor_sync(0xffffffffu, s, 1);
        s += __shfl_xor_sync(0xffffffffu, s, 2);
        if (part==0) sm->a.qs[o] = clip100(s + P.bq[h*64+o]);
    }
    __syncthreads();
    const float* kp = P.Kh + ((size_t)b*Ss + tid)*Hh + h*64;
    float s = 0.f;
    #pragma unroll
    for (int d=0; d<64; d+=4){
        float4 kv = *(const float4*)(kp + d);
        s += sm->a.qs[d]*kv.x + sm->a.qs[d+1]*kv.y + sm->a.qs[d+2]*kv.z + sm->a.qs[d+3]*kv.w;
    }
    s *= 0.125f;
    if (P.mask[b*Ss + tid] == 0) s = -10000.f;
    sm->a.red[tid] = s;
    __syncthreads();
    #pragma unroll
    for (int off=128; off>0; off>>=1){
        if (tid < off) sm->a.red[tid] = fmaxf(sm->a.red[tid], sm->a.red[tid+off]);
        __syncthreads();
    }
    float mx = sm->a.red[0];
    __syncthreads();
    float e = expf(s - mx);
    sm->a.sc[tid] = e;
    sm->a.red[tid] = e;
    __syncthreads();
    #pragma unroll
    for (int off=128; off>0; off>>=1){
        if (tid < off) sm->a.red[tid] += sm->a.red[tid+off];
        __syncthreads();
    }
    float inv = 1.f / sm->a.red[0];
    __syncthreads();
    int d = tid & 63, part = tid >> 6;
    const float* vp = P.Vh + (size_t)b*Ss*Hh + h*64 + d;
    float p = 0.f;
    #pragma unroll 4
    for (int s2 = part*64; s2 < part*64 + 64; s2++)
        p += sm->a.sc[s2] * vp[(size_t)s2*Hh];
    sm->a.psum[part][d] = p;
    __syncthreads();
    if (tid < 64){
        float r = (sm->a.psum[0][tid]+sm->a.psum[1][tid]+sm->a.psum[2][tid]+sm->a.psum[3][tid]) * inv;
        P.ctxp[b*Hh + h*64 + tid] = r;
    }
}

__device__ void ew0_task(const Params& P, int i){
    int base = i*1024 + threadIdx.x;
    #pragma unroll
    for (int e=0;e<4;e++){
        int idx = base + e*256;
        int m = idx >> 9, j = idx & 511;
        int g = m*1536 + j;
        float r = sigm(P.gi0[g]       + P.gh0[g]);
        float z = sigm(P.gi0[g+512]   + P.gh0[g+512]);
        float n = tanhf(P.gi0[g+1024] + r*P.gh0[g+1024]);
        float hv = (1.f - z)*n + z*P.h0[idx];
        P.h0p[idx] = hv;
        P.h0[idx]  = fminf(fmaxf(hv,-10.f),10.f);
    }
}

__device__ void ew1_task(const Params& P, int i, int t){
    int base = i*1024 + threadIdx.x;
    #pragma unroll
    for (int e=0;e<4;e++){
        int idx = base + e*256;
        int m = idx >> 9, j = idx & 511;
        int g = m*1536 + j;
        float r = sigm(P.gi1[g]       + P.gh1[g]);
        float z = sigm(P.gi1[g+512]   + P.gh1[g+512]);
        float n = tanhf(P.gi1[g+1024] + r*P.gh1[g+1024]);
        float hv = (1.f - z)*n + z*P.h1[idx];
        P.h1[idx] = fminf(fmaxf(hv,-10.f),10.f);
        float* cb = P.comb + (size_t)t*Bb*2*Hh + m*1024;
        cb[j]       = hv;            // pre-clip h1
        cb[512 + j] = P.ctx[idx];
    }
}

// variadic: body may contain commas (template args, call args)
#define RUN_PHASE(cidx_, nt_, ...)                                    \
    while (true){                                                     \
        __syncthreads();                                              \
        if (tid==0) s_task = (int)atomicAdd(&g_task[cidx_], 1u);      \
        __syncthreads();                                              \
        const int ti = s_task;                                        \
        if (ti >= (nt_)) break;                                       \
        __VA_ARGS__                                                   \
    }                                                                 \
    grid_bar();

__global__ void __launch_bounds__(256, 1) decoder_loop_kernel(Params P){
    __shared__ SmemU sm;
    __shared__ int s_task;
    __shared__ int s_row[32];
    const int tid = threadIdx.x;

    for (int t = 0; t < STEPS; t++){
        const int cb = t*NPHASE;
        // Phase A: attention (incl. q proj), gh0, gh1, emb
        RUN_PHASE(cb+0, 368, {
            if (ti < 256){
                attn_task(&sm, P, ti>>3, ti&7);
            } else if (ti < 304){
                int c = ti-256;
                gemm_task<4,0>(&sm, c*32, P.h0, nullptr, 512, P.w_hh0, P.b_hh0, P.gh0, 1536, 0, nullptr);
            } else if (ti < 352){
                int c = ti-304;
                gemm_task<4,0>(&sm, c*32, P.h1, nullptr, 512, P.w_hh1, P.b_hh1, P.gh1, 1536, 0, nullptr);
            } else {
                int c = ti-352;
                if (tid < 32) s_row[tid] = P.tgt[tid*Tt + t];
                __syncthreads();
                gemm_task<4,1>(&sm, c*32, P.embt, nullptr, 256, P.w_ep, P.b_ep, P.emb, 512, 0, s_row);
            }
        })
        // Phase B: ctx = clip(ctxp @ wo^T + bo)
        RUN_PHASE(cb+1, 32, {
            gemm_task<2,0>(&sm, ti*16, P.ctxp, nullptr, 512, P.wo, P.bo, P.ctx, 512, 1, nullptr);
        })
        // Phase C: gi0 = [emb, ctx] @ w_ih0^T + b_ih0
        RUN_PHASE(cb+2, 96, {
            gemm_task<2,2>(&sm, ti*16, P.emb, P.ctx, 1024, P.w_ih0, P.b_ih0, P.gi0, 1536, 0, nullptr);
        })
        // Phase D: GRU0 elementwise
        RUN_PHASE(cb+3, 16, { ew0_task(P, ti); })
        // Phase E: gi1 = h0p @ w_ih1^T + b_ih1
        RUN_PHASE(cb+4, 96, {
            gemm_task<2,0>(&sm, ti*16, P.h0p, nullptr, 512, P.w_ih1, P.b_ih1, P.gi1, 1536, 0, nullptr);
        })
        // Phase F: GRU1 elementwise + comb store
        RUN_PHASE(cb+5, 16, { ew1_task(P, ti, t); })
    }
}

// ---------------- driver -------------------------------------------------------
extern "C" void kernel_launch(void* const* d_in, const int* in_sizes, int n_in,
                              void* d_out, int out_size){
    const int*   tgt   = (const int*)  d_in[0];
    const float* enc   = (const float*)d_in[1];
    const float* dec   = (const float*)d_in[2];
    const int*   mask  = (const int*)  d_in[3];
    const float* embt  = (const float*)d_in[4];
    const float* w_ep  = (const float*)d_in[5];
    const float* b_ep  = (const float*)d_in[6];
    const float* wq    = (const float*)d_in[7];
    const float* bq    = (const float*)d_in[8];
    const float* wk    = (const float*)d_in[9];
    const float* bk    = (const float*)d_in[10];
    const float* wv    = (const float*)d_in[11];
    const float* bv    = (const float*)d_in[12];
    const float* wo    = (const float*)d_in[13];
    const float* bo    = (const float*)d_in[14];
    const float* w_ih0 = (const float*)d_in[15];
    const float* w_hh0 = (const float*)d_in[16];
    const float* b_ih0 = (const float*)d_in[17];
    const float* b_hh0 = (const float*)d_in[18];
    const float* w_ih1 = (const float*)d_in[19];
    const float* w_hh1 = (const float*)d_in[20];
    const float* b_ih1 = (const float*)d_in[21];
    const float* b_hh1 = (const float*)d_in[22];
    const float* w_o1  = (const float*)d_in[23];
    const float* b_o1  = (const float*)d_in[24];
    const float* w_o2  = (const float*)d_in[25];
    const float* b_o2  = (const float*)d_in[26];
    float* out = (float*)d_out;

    float* buf = nullptr;
    cudaGetSymbolAddress((void**)&buf, g_buf);

    Params P;
    P.tgt = tgt; P.mask = mask;
    P.embt = embt; P.w_ep = w_ep; P.b_ep = b_ep;
    P.wq = wq; P.bq = bq; P.wo = wo; P.bo = bo;
    P.w_ih0 = w_ih0; P.w_hh0 = w_hh0; P.b_ih0 = b_ih0; P.b_hh0 = b_hh0;
    P.w_ih1 = w_ih1; P.w_hh1 = w_hh1; P.b_ih1 = b_ih1; P.b_hh1 = b_hh1;
    P.Kh = buf + O_KH; P.Vh = buf + O_VH;
    P.h0 = buf + O_H0; P.h1 = buf + O_H1; P.h0p = buf + O_H0P;
    P.emb = buf + O_EMB; P.ctxp = buf + O_CTXP; P.ctx = buf + O_CTX;
    P.gh0 = buf + O_GH0; P.gh1 = buf + O_GH1;
    P.gi0 = buf + O_GI0; P.gi1 = buf + O_GI1;
    P.comb = buf + O_COMB;
    float* o1 = buf + O_O1;

    reset_kernel<<<2, 256>>>();
    init_kernel<<<(Bb*Hh+255)/256, 256>>>(dec, P.h0, P.h1);
    zero_kernel<<<(Bb*Vv+255)/256, 256>>>(out);

    // step-invariant K/V projections (Kh clipped, Vh plain)
    gemm128_kernel<<<dim3(Hh/128, (Bb*Ss)/128), 256>>>(enc, wk, bk, (float*)P.Kh, Bb*Ss, Hh, Hh, 1);
    gemm128_kernel<<<dim3(Hh/128, (Bb*Ss)/128), 256>>>(enc, wv, bv, (float*)P.Vh, Bb*Ss, Hh, Hh, 0);

    // full 63-step recurrence in one persistent kernel
    decoder_loop_kernel<<<NBLK, 256>>>(P);

    // batched output MLP over all 63 steps
    gemm128_kernel<<<dim3(Hh/128, (STEPS*Bb+127)/128), 256>>>(
        P.comb, w_o1, b_o1, o1, STEPS*Bb, Hh, 2*Hh, 2);           // relu
    gemm128_kernel<<<dim3(Vv/128, (STEPS*Bb+127)/128), 256>>>(
        o1, w_o2, b_o2, out, STEPS*Bb, Vv, Hh, 3);                // clip + scatter
}

// round 5
// speedup vs baseline: 3.1441x; 1.0809x over previous
#include <cuda_runtime.h>
#include <math.h>

#define Bb 32
#define Tt 64
#define Ss 256
#define Hh 512
#define Ee 256
#define Vv 32000
#define NHh 8
#define STEPS 63
#define NBLK2 296

// ---------------- scratch ----------------------------------------------------
#define O_KH   0
#define O_VH   (O_KH  + Bb*Ss*Hh)
#define O_H0   (O_VH  + Bb*Ss*Hh)
#define O_H1   (O_H0  + Bb*Hh)
#define O_H0P  (O_H1  + Bb*Hh)
#define O_EMB  (O_H0P + Bb*Hh)
#define O_CTXP (O_EMB + Bb*Hh)
#define O_CTX  (O_CTXP+ Bb*Hh)
#define O_GH0  (O_CTX + Bb*Hh)
#define O_GH1  (O_GH0 + Bb*3*Hh)
#define O_GI0  (O_GH1 + Bb*3*Hh)
#define O_GI1  (O_GI0 + Bb*3*Hh)
#define O_COMB (O_GI1 + Bb*3*Hh)
#define O_O1   (O_COMB + STEPS*Bb*2*Hh)
#define O_TOTAL (O_O1 + STEPS*Bb*Hh)

__device__ float g_buf[O_TOTAL];
__device__ unsigned g_cnt;
__device__ unsigned g_gen;

__device__ __forceinline__ float clip100(float v){ return fminf(fmaxf(v,-100.f),100.f); }
__device__ __forceinline__ float sigm(float x){ return 1.f/(1.f+expf(-x)); }

// ---------------- init & zero ------------------------------------------------
__global__ void init_kernel(const float* __restrict__ dec, float* h0, float* h1){
    int i = blockIdx.x*256 + threadIdx.x;
    if (i < Bb*Hh){
        float v = fminf(fmaxf(dec[i], -10.f), 10.f);
        h0[i] = v; h1[i] = v;
    }
}

__global__ void reset_kernel(){
    if (threadIdx.x == 0 && blockIdx.x == 0){ g_cnt = 0u; g_gen = 0u; }
}

__global__ void zero_kernel(float* __restrict__ out){
    int i = blockIdx.x*256 + threadIdx.x;
    if (i < Bb*Vv){
        int b = i / Vv, v = i % Vv;
        out[(size_t)b*Tt*Vv + v] = 0.f;
    }
}

// ---------------- big tiled SGEMM (for KV proj + output MLP) ------------------
// mode: 0 plain, 1 clip100, 2 relu, 3 clip100 + scatter into [B,T,V] at t+1
__global__ void gemm128_kernel(const float* __restrict__ A, const float* __restrict__ W,
                               const float* __restrict__ bias, float* __restrict__ C,
                               int M, int N, int K, int mode){
    __shared__ float As[8][128];
    __shared__ float Ws[8][128];
    const int tid = threadIdx.x;
    const int bm = blockIdx.y * 128;
    const int bn = blockIdx.x * 128;
    const int lrow = tid >> 1;
    const int lk4  = (tid & 1) * 4;
    const int tx = tid & 15, ty = tid >> 4;

    float acc[8][8];
    #pragma unroll
    for (int i=0;i<8;i++)
        #pragma unroll
        for (int j=0;j<8;j++) acc[i][j]=0.f;

    for (int kb = 0; kb < K; kb += 8){
        float4 av = make_float4(0.f,0.f,0.f,0.f);
        int ar = bm + lrow;
        if (ar < M) av = *(const float4*)(A + (size_t)ar*K + kb + lk4);
        As[lk4+0][lrow]=av.x; As[lk4+1][lrow]=av.y; As[lk4+2][lrow]=av.z; As[lk4+3][lrow]=av.w;
        float4 wv = *(const float4*)(W + (size_t)(bn+lrow)*K + kb + lk4);
        Ws[lk4+0][lrow]=wv.x; Ws[lk4+1][lrow]=wv.y; Ws[lk4+2][lrow]=wv.z; Ws[lk4+3][lrow]=wv.w;
        __syncthreads();
        #pragma unroll
        for (int k=0;k<8;k++){
            float4 a0 = *(const float4*)&As[k][ty*4];
            float4 a1 = *(const float4*)&As[k][64 + ty*4];
            float4 b0 = *(const float4*)&Ws[k][tx*4];
            float4 b1 = *(const float4*)&Ws[k][64 + tx*4];
            float am[8] = {a0.x,a0.y,a0.z,a0.w, a1.x,a1.y,a1.z,a1.w};
            float bm_[8]= {b0.x,b0.y,b0.z,b0.w, b1.x,b1.y,b1.z,b1.w};
            #pragma unroll
            for (int i=0;i<8;i++)
                #pragma unroll
                for (int j=0;j<8;j++)
                    acc[i][j] += am[i]*bm_[j];
        }
        __syncthreads();
    }

    #pragma unroll
    for (int i=0;i<8;i++){
        int gm = bm + (i<4 ? ty*4+i : 64 + ty*4 + (i-4));
        if (gm >= M) continue;
        #pragma unroll
        for (int j=0;j<8;j++){
            int gn = bn + (j<4 ? tx*4+j : 64 + tx*4 + (j-4));
            float v = acc[i][j] + bias[gn];
            if (mode==1 || mode==3) v = clip100(v);
            else if (mode==2)       v = fmaxf(v, 0.f);
            if (mode==3){
                int b = gm & 31, t = gm >> 5;
                C[((size_t)b*Tt + t + 1)*Vv + gn] = v;
            } else {
                C[(size_t)gm*N + gn] = v;
            }
        }
    }
}

// ---------------- persistent decoder loop -------------------------------------
struct SmemG { float As[32*132]; float Ws[32*128]; };
struct SmemA { float hs[512]; float qs[64]; float sc[256]; float red[256]; float psum[4][64]; };
union SmemU { SmemG g; SmemA a; };

struct Params {
    const int*   tgt;  const int* mask;
    const float* embt; const float* w_ep; const float* b_ep;
    const float* wq;   const float* bq;
    const float* wo;   const float* bo;
    const float* w_ih0; const float* w_hh0; const float* b_ih0; const float* b_hh0;
    const float* w_ih1; const float* w_hh1; const float* b_ih1; const float* b_hh1;
    const float* Kh; const float* Vh;
    float *h0, *h1, *h0p, *emb, *ctxp, *ctx, *gh0, *gh1, *gi0, *gi1, *comb;
};

// monotonic-generation grid barrier: no counter reset, hard spin with acquire loads
__device__ __forceinline__ void grid_bar(unsigned target){
    __syncthreads();
    if (threadIdx.x == 0){
        __threadfence();   // publish writes + CCTL.IVALL (L1 coherence across SMs)
        unsigned prev = atomicAdd(&g_cnt, 1u);
        if (prev == target*NBLK2 - 1u){
            asm volatile("st.release.gpu.u32 [%0], %1;" :: "l"(&g_gen), "r"(target) : "memory");
        } else {
            unsigned v;
            do {
                asm volatile("ld.acquire.gpu.u32 %0, [%1];" : "=r"(v) : "l"(&g_gen) : "memory");
            } while (v < target);
        }
    }
    __syncthreads();
}

// M=32 GEMM: lane = m (A row in registers), W broadcast from smem.
// AK: 0 plain (lda=512), 1 gather rows (embt, lda=256), 2 concat [emb|ctx]
template<int NW, int AK>
__device__ void gemm_task(SmemU* sm, int n0,
                          const float* __restrict__ A, const float* __restrict__ A2,
                          int K, const float* __restrict__ W, const float* __restrict__ bias,
                          float* __restrict__ C, int ldc, int act, const int* sRow)
{
    const int tid = threadIdx.x;
    const int lane = tid & 31;
    const int wp = tid >> 5;
    float acc[NW];
    #pragma unroll
    for (int i=0;i<NW;i++) acc[i]=0.f;

    for (int kb=0; kb<K; kb+=128){
        #pragma unroll
        for (int p=0;p<4;p++){
            int idx = tid + p*256;
            int r = idx >> 5, c4 = (idx & 31)*4;
            float4 v;
            if (AK==0) v = *(const float4*)(A + r*512 + kb + c4);
            else if (AK==1) v = *(const float4*)(A + sRow[r]*Ee + kb + c4);
            else { int kk = kb + c4;
                   v = (kk < 512) ? *(const float4*)(A + r*512 + kk)
                                  : *(const float4*)(A2 + r*512 + kk - 512); }
            *(float4*)&sm->g.As[r*132 + c4] = v;
        }
        const int nTask = NW*8;
        for (int idx = tid; idx < nTask*32; idx += 256){
            int n = idx >> 5, c4 = (idx & 31)*4;
            *(float4*)&sm->g.Ws[n*128 + c4] = *(const float4*)(W + (size_t)(n0+n)*K + kb + c4);
        }
        __syncthreads();
        #pragma unroll
        for (int kc=0; kc<128; kc+=32){
            float a[32];
            #pragma unroll
            for (int j=0;j<32;j+=4)
                *(float4*)&a[j] = *(const float4*)&sm->g.As[lane*132 + kc + j];
            #pragma unroll
            for (int nn=0;nn<NW;nn++){
                const float* wr = &sm->g.Ws[(wp*NW+nn)*128 + kc];
                float s0=0.f, s1=0.f;
                #pragma unroll
                for (int j=0;j<32;j+=8){
                    float4 w0 = *(const float4*)(wr + j);
                    float4 w1 = *(const float4*)(wr + j + 4);
                    s0 += a[j+0]*w0.x + a[j+1]*w0.y + a[j+2]*w0.z + a[j+3]*w0.w;
                    s1 += a[j+4]*w1.x + a[j+5]*w1.y + a[j+6]*w1.z + a[j+7]*w1.w;
                }
                acc[nn] += s0 + s1;
            }
        }
        __syncthreads();
    }
    #pragma unroll
    for (int nn=0;nn<NW;nn++){
        int n = n0 + wp*NW + nn;
        float v = acc[nn] + bias[n];
        if (act) v = clip100(v);
        C[lane*ldc + n] = v;
    }
}

// fused q-projection + attention for one (b, head)
__device__ void attn_task(SmemU* sm, const Params& P, int b, int h){
    const int tid = threadIdx.x;
    for (int i=tid; i<512; i+=256) sm->a.hs[i] = P.h1[b*Hh + i];
    __syncthreads();
    {
        int o = tid >> 2, part = tid & 3;
        const float* wr = P.wq + (size_t)(h*64 + o)*Hh + part*128;
        const float* hp = sm->a.hs + part*128;
        float s = 0.f;
        #pragma unroll
        for (int j=0;j<128;j+=4){
            float4 wv = *(const float4*)(wr + j);
            s += hp[j]*wv.x + hp[j+1]*wv.y + hp[j+2]*wv.z + hp[j+3]*wv.w;
        }
        s += __shfl_xor_sync(0xffffffffu, s, 1);
        s += __shfl_xor_sync(0xffffffffu, s, 2);
        if (part==0) sm->a.qs[o] = clip100(s + P.bq[h*64+o]);
    }
    __syncthreads();
    const float* kp = P.Kh + ((size_t)b*Ss + tid)*Hh + h*64;
    float s = 0.f;
    #pragma unroll
    for (int d=0; d<64; d+=4){
        float4 kv = *(const float4*)(kp + d);
        s += sm->a.qs[d]*kv.x + sm->a.qs[d+1]*kv.y + sm->a.qs[d+2]*kv.z + sm->a.qs[d+3]*kv.w;
    }
    s *= 0.125f;
    if (P.mask[b*Ss + tid] == 0) s = -10000.f;
    sm->a.red[tid] = s;
    __syncthreads();
    #pragma unroll
    for (int off=128; off>0; off>>=1){
        if (tid < off) sm->a.red[tid] = fmaxf(sm->a.red[tid], sm->a.red[tid+off]);
        __syncthreads();
    }
    float mx = sm->a.red[0];
    __syncthreads();
    float e = expf(s - mx);
    sm->a.sc[tid] = e;
    sm->a.red[tid] = e;
    __syncthreads();
    #pragma unroll
    for (int off=128; off>0; off>>=1){
        if (tid < off) sm->a.red[tid] += sm->a.red[tid+off];
        __syncthreads();
    }
    float inv = 1.f / sm->a.red[0];
    __syncthreads();
    int d = tid & 63, part = tid >> 6;
    const float* vp = P.Vh + (size_t)b*Ss*Hh + h*64 + d;
    float p = 0.f;
    #pragma unroll 4
    for (int s2 = part*64; s2 < part*64 + 64; s2++)
        p += sm->a.sc[s2] * vp[(size_t)s2*Hh];
    sm->a.psum[part][d] = p;
    __syncthreads();
    if (tid < 64){
        float r = (sm->a.psum[0][tid]+sm->a.psum[1][tid]+sm->a.psum[2][tid]+sm->a.psum[3][tid]) * inv;
        P.ctxp[b*Hh + h*64 + tid] = r;
    }
}

__device__ void ew0_task(const Params& P, int i){
    int base = i*1024 + threadIdx.x;
    #pragma unroll
    for (int e=0;e<4;e++){
        int idx = base + e*256;
        int m = idx >> 9, j = idx & 511;
        int g = m*1536 + j;
        float r = sigm(P.gi0[g]       + P.gh0[g]);
        float z = sigm(P.gi0[g+512]   + P.gh0[g+512]);
        float n = tanhf(P.gi0[g+1024] + r*P.gh0[g+1024]);
        float hv = (1.f - z)*n + z*P.h0[idx];
        P.h0p[idx] = hv;
        P.h0[idx]  = fminf(fmaxf(hv,-10.f),10.f);
    }
}

__device__ void ew1_task(const Params& P, int i, int t){
    int base = i*1024 + threadIdx.x;
    #pragma unroll
    for (int e=0;e<4;e++){
        int idx = base + e*256;
        int m = idx >> 9, j = idx & 511;
        int g = m*1536 + j;
        float r = sigm(P.gi1[g]       + P.gh1[g]);
        float z = sigm(P.gi1[g+512]   + P.gh1[g+512]);
        float n = tanhf(P.gi1[g+1024] + r*P.gh1[g+1024]);
        float hv = (1.f - z)*n + z*P.h1[idx];
        P.h1[idx] = fminf(fmaxf(hv,-10.f),10.f);
        float* cb = P.comb + (size_t)t*Bb*2*Hh + m*1024;
        cb[j]       = hv;            // pre-clip h1
        cb[512 + j] = P.ctx[idx];
    }
}

// static task loop: block handles ti = bid, bid+NBLK2, ...
#define PHASE(nt_, ...)                                               \
    for (int ti = (int)blockIdx.x; ti < (nt_); ti += NBLK2){          \
        __syncthreads();                                              \
        __VA_ARGS__                                                   \
    }                                                                 \
    bar++; grid_bar(bar);

__global__ void __launch_bounds__(256, 2) decoder_loop_kernel(Params P){
    __shared__ SmemU sm;
    __shared__ int s_row[32];
    const int tid = threadIdx.x;
    unsigned bar = 0;

    for (int t = 0; t < STEPS; t++){
        // Phase A: attention(256) + gh0(96) + gh1(96) + emb(32) = 480 tasks
        PHASE(480, {
            if (ti < 256){
                attn_task(&sm, P, ti>>3, ti&7);
            } else if (ti < 352){
                gemm_task<2,0>(&sm, (ti-256)*16, P.h0, nullptr, 512, P.w_hh0, P.b_hh0, P.gh0, 1536, 0, nullptr);
            } else if (ti < 448){
                gemm_task<2,0>(&sm, (ti-352)*16, P.h1, nullptr, 512, P.w_hh1, P.b_hh1, P.gh1, 1536, 0, nullptr);
            } else {
                if (tid < 32) s_row[tid] = P.tgt[tid*Tt + t];
                __syncthreads();
                gemm_task<2,1>(&sm, (ti-448)*16, P.embt, nullptr, 256, P.w_ep, P.b_ep, P.emb, 512, 0, s_row);
            }
        })
        // Phase B: ctx = clip(ctxp @ wo^T + bo)  (64 tasks x 8 cols)
        PHASE(64, {
            gemm_task<1,0>(&sm, ti*8, P.ctxp, nullptr, 512, P.wo, P.bo, P.ctx, 512, 1, nullptr);
        })
        // Phase C: gi0 = [emb, ctx] @ w_ih0^T + b_ih0  (192 tasks x 8 cols)
        PHASE(192, {
            gemm_task<1,2>(&sm, ti*8, P.emb, P.ctx, 1024, P.w_ih0, P.b_ih0, P.gi0, 1536, 0, nullptr);
        })
        // Phase D: GRU0 elementwise
        PHASE(16, { ew0_task(P, ti); })
        // Phase E: gi1 = h0p @ w_ih1^T + b_ih1  (192 tasks x 8 cols)
        PHASE(192, {
            gemm_task<1,0>(&sm, ti*8, P.h0p, nullptr, 512, P.w_ih1, P.b_ih1, P.gi1, 1536, 0, nullptr);
        })
        // Phase F: GRU1 elementwise + comb store
        PHASE(16, { ew1_task(P, ti, t); })
    }
}

// ---------------- driver -------------------------------------------------------
extern "C" void kernel_launch(void* const* d_in, const int* in_sizes, int n_in,
                              void* d_out, int out_size){
    const int*   tgt   = (const int*)  d_in[0];
    const float* enc   = (const float*)d_in[1];
    const float* dec   = (const float*)d_in[2];
    const int*   mask  = (const int*)  d_in[3];
    const float* embt  = (const float*)d_in[4];
    const float* w_ep  = (const float*)d_in[5];
    const float* b_ep  = (const float*)d_in[6];
    const float* wq    = (const float*)d_in[7];
    const float* bq    = (const float*)d_in[8];
    const float* wk    = (const float*)d_in[9];
    const float* bk    = (const float*)d_in[10];
    const float* wv    = (const float*)d_in[11];
    const float* bv    = (const float*)d_in[12];
    const float* wo    = (const float*)d_in[13];
    const float* bo    = (const float*)d_in[14];
    const float* w_ih0 = (const float*)d_in[15];
    const float* w_hh0 = (const float*)d_in[16];
    const float* b_ih0 = (const float*)d_in[17];
    const float* b_hh0 = (const float*)d_in[18];
    const float* w_ih1 = (const float*)d_in[19];
    const float* w_hh1 = (const float*)d_in[20];
    const float* b_ih1 = (const float*)d_in[21];
    const float* b_hh1 = (const float*)d_in[22];
    const float* w_o1  = (const float*)d_in[23];
    const float* b_o1  = (const float*)d_in[24];
    const float* w_o2  = (const float*)d_in[25];
    const float* b_o2  = (const float*)d_in[26];
    float* out = (float*)d_out;

    float* buf = nullptr;
    cudaGetSymbolAddress((void**)&buf, g_buf);

    Params P;
    P.tgt = tgt; P.mask = mask;
    P.embt = embt; P.w_ep = w_ep; P.b_ep = b_ep;
    P.wq = wq; P.bq = bq; P.wo = wo; P.bo = bo;
    P.w_ih0 = w_ih0; P.w_hh0 = w_hh0; P.b_ih0 = b_ih0; P.b_hh0 = b_hh0;
    P.w_ih1 = w_ih1; P.w_hh1 = w_hh1; P.b_ih1 = b_ih1; P.b_hh1 = b_hh1;
    P.Kh = buf + O_KH; P.Vh = buf + O_VH;
    P.h0 = buf + O_H0; P.h1 = buf + O_H1; P.h0p = buf + O_H0P;
    P.emb = buf + O_EMB; P.ctxp = buf + O_CTXP; P.ctx = buf + O_CTX;
    P.gh0 = buf + O_GH0; P.gh1 = buf + O_GH1;
    P.gi0 = buf + O_GI0; P.gi1 = buf + O_GI1;
    P.comb = buf + O_COMB;
    float* o1 = buf + O_O1;

    reset_kernel<<<1, 32>>>();
    init_kernel<<<(Bb*Hh+255)/256, 256>>>(dec, P.h0, P.h1);
    zero_kernel<<<(Bb*Vv+255)/256, 256>>>(out);

    // step-invariant K/V projections (Kh clipped, Vh plain)
    gemm128_kernel<<<dim3(Hh/128, (Bb*Ss)/128), 256>>>(enc, wk, bk, (float*)P.Kh, Bb*Ss, Hh, Hh, 1);
    gemm128_kernel<<<dim3(Hh/128, (Bb*Ss)/128), 256>>>(enc, wv, bv, (float*)P.Vh, Bb*Ss, Hh, Hh, 0);

    // full 63-step recurrence in one persistent kernel
    decoder_loop_kernel<<<NBLK2, 256>>>(P);

    // batched output MLP over all 63 steps
    gemm128_kernel<<<dim3(Hh/128, (STEPS*Bb+127)/128), 256>>>(
        P.comb, w_o1, b_o1, o1, STEPS*Bb, Hh, 2*Hh, 2);           // relu
    gemm128_kernel<<<dim3(Vv/128, (STEPS*Bb+127)/128), 256>>>(
        o1, w_o2, b_o2, out, STEPS*Bb, Vv, Hh, 3);                // clip + scatter
}

// round 6
// speedup vs baseline: 3.2740x; 1.0413x over previous
#include <cuda_runtime.h>
#include <math.h>

#define Bb 32
#define Tt 64
#define Ss 256
#define Hh 512
#define Ee 256
#define Vv 32000
#define NHh 8
#define STEPS 63
#define NBLK2 296

// ---------------- scratch ----------------------------------------------------
#define O_KH   0
#define O_VH   (O_KH  + Bb*Ss*Hh)
#define O_H0   (O_VH  + Bb*Ss*Hh)
#define O_H1   (O_H0  + Bb*Hh)
#define O_H0P  (O_H1  + Bb*Hh)
#define O_EMB  (O_H0P + Bb*Hh)
#define O_CTXR (O_EMB + Bb*Hh)
#define O_GH0  (O_CTXR+ 2*Bb*Hh)
#define O_GH1  (O_GH0 + Bb*3*Hh)
#define O_GI0  (O_GH1 + Bb*3*Hh)
#define O_GI1  (O_GI0 + Bb*3*Hh)
#define O_COMB (O_GI1 + Bb*3*Hh)
#define O_O1   (O_COMB + STEPS*Bb*2*Hh)
#define O_TOTAL (O_O1 + STEPS*Bb*Hh)

__device__ float g_buf[O_TOTAL];
// barrier words on separate L2 lines (avoid atomic/poll line conflict)
__device__ unsigned g_cnt_arr[64];
__device__ unsigned g_gen_arr[64];

__device__ __forceinline__ float clip100(float v){ return fminf(fmaxf(v,-100.f),100.f); }
__device__ __forceinline__ float sigm(float x){ return 1.f/(1.f+expf(-x)); }

// ---------------- init & zero ------------------------------------------------
__global__ void init_kernel(const float* __restrict__ dec, const float* __restrict__ bo,
                            float* h0, float* h1, float* ctxr0){
    int i = blockIdx.x*256 + threadIdx.x;
    if (i < Bb*Hh){
        float v = fminf(fmaxf(dec[i], -10.f), 10.f);
        h0[i] = v; h1[i] = v;
        ctxr0[i] = bo[i & 511];      // ctx accumulator buf0 starts at bias
    }
}

__global__ void reset_kernel(){
    if (threadIdx.x == 0 && blockIdx.x == 0){ g_cnt_arr[0] = 0u; g_gen_arr[0] = 0u; }
}

__global__ void zero_kernel(float* __restrict__ out){
    int i = blockIdx.x*256 + threadIdx.x;
    if (i < Bb*Vv){
        int b = i / Vv, v = i % Vv;
        out[(size_t)b*Tt*Vv + v] = 0.f;
    }
}

// ---------------- big tiled SGEMM (for KV proj + output MLP) ------------------
// mode: 0 plain, 1 clip100, 2 relu, 3 clip100 + scatter into [B,T,V] at t+1
__global__ void gemm128_kernel(const float* __restrict__ A, const float* __restrict__ W,
                               const float* __restrict__ bias, float* __restrict__ C,
                               int M, int N, int K, int mode){
    __shared__ float As[8][128];
    __shared__ float Ws[8][128];
    const int tid = threadIdx.x;
    const int bm = blockIdx.y * 128;
    const int bn = blockIdx.x * 128;
    const int lrow = tid >> 1;
    const int lk4  = (tid & 1) * 4;
    const int tx = tid & 15, ty = tid >> 4;

    float acc[8][8];
    #pragma unroll
    for (int i=0;i<8;i++)
        #pragma unroll
        for (int j=0;j<8;j++) acc[i][j]=0.f;

    for (int kb = 0; kb < K; kb += 8){
        float4 av = make_float4(0.f,0.f,0.f,0.f);
        int ar = bm + lrow;
        if (ar < M) av = *(const float4*)(A + (size_t)ar*K + kb + lk4);
        As[lk4+0][lrow]=av.x; As[lk4+1][lrow]=av.y; As[lk4+2][lrow]=av.z; As[lk4+3][lrow]=av.w;
        float4 wv = *(const float4*)(W + (size_t)(bn+lrow)*K + kb + lk4);
        Ws[lk4+0][lrow]=wv.x; Ws[lk4+1][lrow]=wv.y; Ws[lk4+2][lrow]=wv.z; Ws[lk4+3][lrow]=wv.w;
        __syncthreads();
        #pragma unroll
        for (int k=0;k<8;k++){
            float4 a0 = *(const float4*)&As[k][ty*4];
            float4 a1 = *(const float4*)&As[k][64 + ty*4];
            float4 b0 = *(const float4*)&Ws[k][tx*4];
            float4 b1 = *(const float4*)&Ws[k][64 + tx*4];
            float am[8] = {a0.x,a0.y,a0.z,a0.w, a1.x,a1.y,a1.z,a1.w};
            float bm_[8]= {b0.x,b0.y,b0.z,b0.w, b1.x,b1.y,b1.z,b1.w};
            #pragma unroll
            for (int i=0;i<8;i++)
                #pragma unroll
                for (int j=0;j<8;j++)
                    acc[i][j] += am[i]*bm_[j];
        }
        __syncthreads();
    }

    #pragma unroll
    for (int i=0;i<8;i++){
        int gm = bm + (i<4 ? ty*4+i : 64 + ty*4 + (i-4));
        if (gm >= M) continue;
        #pragma unroll
        for (int j=0;j<8;j++){
            int gn = bn + (j<4 ? tx*4+j : 64 + tx*4 + (j-4));
            float v = acc[i][j] + bias[gn];
            if (mode==1 || mode==3) v = clip100(v);
            else if (mode==2)       v = fmaxf(v, 0.f);
            if (mode==3){
                int b = gm & 31, t = gm >> 5;
                C[((size_t)b*Tt + t + 1)*Vv + gn] = v;
            } else {
                C[(size_t)gm*N + gn] = v;
            }
        }
    }
}

// ---------------- persistent decoder loop -------------------------------------
struct SmemG { float As[32*132]; float Ws[32*128]; };
struct SmemA { float hs[512]; float qs[64]; float sc[256]; float red[256];
               float psum[4][64]; float ctxv[64]; };
union SmemU { SmemG g; SmemA a; };

struct Params {
    const int*   tgt;  const int* mask;
    const float* embt; const float* w_ep; const float* b_ep;
    const float* wq;   const float* bq;
    const float* wo;   const float* bo;
    const float* w_ih0; const float* w_hh0; const float* b_ih0; const float* b_hh0;
    const float* w_ih1; const float* w_hh1; const float* b_ih1; const float* b_hh1;
    const float* Kh; const float* Vh;
    float *h0, *h1, *h0p, *emb, *ctxr, *gh0, *gh1, *gi0, *gi1, *comb;
};

__device__ __forceinline__ void grid_bar(unsigned target){
    __syncthreads();
    if (threadIdx.x == 0){
        __threadfence();
        unsigned prev = atomicAdd(&g_cnt_arr[0], 1u);
        if (prev == target*NBLK2 - 1u){
            __threadfence();
            asm volatile("st.release.gpu.u32 [%0], %1;" :: "l"(&g_gen_arr[0]), "r"(target) : "memory");
        } else {
            unsigned v;
            do {
                asm volatile("ld.acquire.gpu.u32 %0, [%1];" : "=r"(v) : "l"(&g_gen_arr[0]) : "memory");
            } while (v < target);
        }
    }
    __syncthreads();
}

// M=32 GEMM with register prefetch of next k-block.
// AK: 0 plain (lda=512), 1 gather rows (embt, lda=256), 2 concat [emb | clip(ctx_raw)]
template<int NW, int AK>
__device__ void gemm_task(SmemU* sm, int n0,
                          const float* __restrict__ A, const float* __restrict__ A2,
                          int K, const float* __restrict__ W, const float* __restrict__ bias,
                          float* __restrict__ C, int ldc, int act, const int* sRow)
{
    const int tid = threadIdx.x;
    const int lane = tid & 31;
    const int wp = tid >> 5;
    float acc[NW];
    #pragma unroll
    for (int i=0;i<NW;i++) acc[i]=0.f;

    float4 pa[4];
    float4 pw[NW];

    // load A tile slice for k-block kb into pa
    auto loadA = [&](int kb){
        #pragma unroll
        for (int p=0;p<4;p++){
            int idx = tid + p*256;
            int r = idx >> 5, c4 = (idx & 31)*4;
            float4 v;
            if (AK==0)      v = *(const float4*)(A + r*512 + kb + c4);
            else if (AK==1) v = *(const float4*)(A + sRow[r]*Ee + kb + c4);
            else {
                int kk = kb + c4;
                if (kk < 512) v = *(const float4*)(A + r*512 + kk);
                else {
                    v = *(const float4*)(A2 + r*512 + kk - 512);
                    v.x = clip100(v.x); v.y = clip100(v.y);
                    v.z = clip100(v.z); v.w = clip100(v.w);
                }
            }
            pa[p] = v;
        }
    };
    auto loadW = [&](int kb){
        #pragma unroll
        for (int q=0;q<NW;q++){
            int idx = tid + q*256;
            int n = idx >> 5, c4 = (idx & 31)*4;
            pw[q] = *(const float4*)(W + (size_t)(n0+n)*K + kb + c4);
        }
    };

    loadA(0); loadW(0);

    for (int kb=0; kb<K; kb+=128){
        __syncthreads();          // previous compute done, smem reusable
        #pragma unroll
        for (int p=0;p<4;p++){
            int idx = tid + p*256;
            int r = idx >> 5, c4 = (idx & 31)*4;
            *(float4*)&sm->g.As[r*132 + c4] = pa[p];
        }
        #pragma unroll
        for (int q=0;q<NW;q++){
            int idx = tid + q*256;
            int n = idx >> 5, c4 = (idx & 31)*4;
            *(float4*)&sm->g.Ws[n*128 + c4] = pw[q];
        }
        __syncthreads();
        if (kb + 128 < K){ loadA(kb+128); loadW(kb+128); }   // overlap with compute
        #pragma unroll
        for (int kc=0; kc<128; kc+=32){
            float a[32];
            #pragma unroll
            for (int j=0;j<32;j+=4)
                *(float4*)&a[j] = *(const float4*)&sm->g.As[lane*132 + kc + j];
            #pragma unroll
            for (int nn=0;nn<NW;nn++){
                const float* wr = &sm->g.Ws[(wp*NW+nn)*128 + kc];
                float s0=0.f, s1=0.f;
                #pragma unroll
                for (int j=0;j<32;j+=8){
                    float4 w0 = *(const float4*)(wr + j);
                    float4 w1 = *(const float4*)(wr + j + 4);
                    s0 += a[j+0]*w0.x + a[j+1]*w0.y + a[j+2]*w0.z + a[j+3]*w0.w;
                    s1 += a[j+4]*w1.x + a[j+5]*w1.y + a[j+6]*w1.z + a[j+7]*w1.w;
                }
                acc[nn] += s0 + s1;
            }
        }
    }
    #pragma unroll
    for (int nn=0;nn<NW;nn++){
        int n = n0 + wp*NW + nn;
        float v = acc[nn] + bias[n];
        if (act) v = clip100(v);
        C[lane*ldc + n] = v;
    }
}

// fused q-projection + attention + wo-partial for (b, head-pair)
__device__ void attn_task(SmemU* smu, const Params& P, int b, int hpair, float* ctxr){
    SmemA* sa = &smu->a;
    const int tid = threadIdx.x;
    for (int i=tid; i<512; i+=256) sa->hs[i] = P.h1[b*Hh + i];
    __syncthreads();

    for (int hh=0; hh<2; hh++){
        const int h = hpair*2 + hh;
        // q projection for this head (64 outputs)
        {
            int o = tid >> 2, part = tid & 3;
            const float* wr = P.wq + (size_t)(h*64 + o)*Hh + part*128;
            const float* hp = sa->hs + part*128;
            float s = 0.f;
            #pragma unroll
            for (int j=0;j<128;j+=4){
                float4 wv = *(const float4*)(wr + j);
                s += hp[j]*wv.x + hp[j+1]*wv.y + hp[j+2]*wv.z + hp[j+3]*wv.w;
            }
            s += __shfl_xor_sync(0xffffffffu, s, 1);
            s += __shfl_xor_sync(0xffffffffu, s, 2);
            if (part==0) sa->qs[o] = clip100(s + P.bq[h*64+o]);
        }
        __syncthreads();
        // scores
        const float* kp = P.Kh + ((size_t)b*Ss + tid)*Hh + h*64;
        float s = 0.f;
        #pragma unroll
        for (int d=0; d<64; d+=4){
            float4 kv = *(const float4*)(kp + d);
            s += sa->qs[d]*kv.x + sa->qs[d+1]*kv.y + sa->qs[d+2]*kv.z + sa->qs[d+3]*kv.w;
        }
        s *= 0.125f;
        if (P.mask[b*Ss + tid] == 0) s = -10000.f;
        sa->red[tid] = s;
        __syncthreads();
        #pragma unroll
        for (int off=128; off>0; off>>=1){
            if (tid < off) sa->red[tid] = fmaxf(sa->red[tid], sa->red[tid+off]);
            __syncthreads();
        }
        float mx = sa->red[0];
        __syncthreads();
        float e = expf(s - mx);
        sa->sc[tid] = e;
        sa->red[tid] = e;
        __syncthreads();
        #pragma unroll
        for (int off=128; off>0; off>>=1){
            if (tid < off) sa->red[tid] += sa->red[tid+off];
            __syncthreads();
        }
        float inv = 1.f / sa->red[0];
        __syncthreads();
        // attn @ V
        {
            int d = tid & 63, part = tid >> 6;
            const float* vp = P.Vh + (size_t)b*Ss*Hh + h*64 + d;
            float p0 = 0.f, p1 = 0.f;
            #pragma unroll 4
            for (int s2 = part*64; s2 < part*64 + 64; s2 += 2){
                p0 += sa->sc[s2]   * vp[(size_t)s2*Hh];
                p1 += sa->sc[s2+1] * vp[(size_t)(s2+1)*Hh];
            }
            sa->psum[part][d] = p0 + p1;
        }
        __syncthreads();
        if (tid < 64)
            sa->ctxv[tid] = (sa->psum[0][tid]+sa->psum[1][tid]+sa->psum[2][tid]+sa->psum[3][tid]) * inv;
        __syncthreads();
        // wo partial: ctx_raw[b, n] += ctxv . wo[n, h*64 : h*64+64]
        #pragma unroll
        for (int rr=0; rr<2; rr++){
            int n = tid + rr*256;
            const float4* wr = (const float4*)(P.wo + (size_t)n*Hh + h*64);
            float s2 = 0.f;
            #pragma unroll
            for (int j=0;j<16;j++){
                float4 w = wr[j];
                s2 += sa->ctxv[j*4+0]*w.x + sa->ctxv[j*4+1]*w.y
                    + sa->ctxv[j*4+2]*w.z + sa->ctxv[j*4+3]*w.w;
            }
            atomicAdd(ctxr + b*Hh + n, s2);
        }
        __syncthreads();
    }
}

__device__ void ew0_task(const Params& P, int ti){
    int idx = ti*256 + threadIdx.x;            // 64 tasks x 256 = 16384
    int m = idx >> 9, j = idx & 511;
    int g = m*1536 + j;
    float r = sigm(P.gi0[g]       + P.gh0[g]);
    float z = sigm(P.gi0[g+512]   + P.gh0[g+512]);
    float n = tanhf(P.gi0[g+1024] + r*P.gh0[g+1024]);
    float hv = (1.f - z)*n + z*P.h0[idx];
    P.h0p[idx] = hv;
    P.h0[idx]  = fminf(fmaxf(hv,-10.f),10.f);
}

__device__ void ew1_task(const Params& P, int ti, int t, const float* ctxr){
    int idx = ti*256 + threadIdx.x;
    int m = idx >> 9, j = idx & 511;
    int g = m*1536 + j;
    float r = sigm(P.gi1[g]       + P.gh1[g]);
    float z = sigm(P.gi1[g+512]   + P.gh1[g+512]);
    float n = tanhf(P.gi1[g+1024] + r*P.gh1[g+1024]);
    float hv = (1.f - z)*n + z*P.h1[idx];
    P.h1[idx] = fminf(fmaxf(hv,-10.f),10.f);
    float* cb = P.comb + (size_t)t*Bb*2*Hh + m*1024;
    cb[j]       = hv;                             // pre-clip h1
    cb[512 + j] = clip100(ctxr[idx]);             // clipped ctx
}

#define PHASE(nt_, ...)                                               \
    for (int ti = (int)blockIdx.x; ti < (nt_); ti += NBLK2){          \
        __syncthreads();                                              \
        __VA_ARGS__                                                   \
    }                                                                 \
    bar++; grid_bar(bar);

__global__ void __launch_bounds__(256, 2) decoder_loop_kernel(Params P){
    __shared__ SmemU sm;
    __shared__ int s_row[32];
    const int tid = threadIdx.x;
    unsigned bar = 0;

    for (int t = 0; t < STEPS; t++){
        float* ctxr_cur  = P.ctxr + (t & 1)*Bb*Hh;
        float* ctxr_next = P.ctxr + ((t+1) & 1)*Bb*Hh;

        // P1: attn(+q+wo partial) x128, gh0 x48, gh1 x48, emb x16  = 240 tasks
        PHASE(240, {
            if (ti < 128){
                attn_task(&sm, P, ti & 31, ti >> 5, ctxr_cur);
            } else if (ti < 176){
                gemm_task<4,0>(&sm, (ti-128)*32, P.h0, nullptr, 512, P.w_hh0, P.b_hh0, P.gh0, 1536, 0, nullptr);
            } else if (ti < 224){
                gemm_task<4,0>(&sm, (ti-176)*32, P.h1, nullptr, 512, P.w_hh1, P.b_hh1, P.gh1, 1536, 0, nullptr);
            } else {
                if (tid < 32) s_row[tid] = P.tgt[tid*Tt + t];
                __syncthreads();
                gemm_task<4,1>(&sm, (ti-224)*32, P.embt, nullptr, 256, P.w_ep, P.b_ep, P.emb, 512, 0, s_row);
            }
        })
        // P2: gi0 = [emb, clip(ctx)] @ w_ih0^T  x192  + init next ctx buffer x8
        PHASE(200, {
            if (ti < 192){
                gemm_task<1,2>(&sm, ti*8, P.emb, ctxr_cur, 1024, P.w_ih0, P.b_ih0, P.gi0, 1536, 0, nullptr);
            } else {
                int base = (ti-192)*2048 + tid;
                #pragma unroll
                for (int e=0;e<8;e++){
                    int idx = base + e*256;
                    ctxr_next[idx] = P.bo[idx & 511];
                }
            }
        })
        // P3: GRU0 elementwise  x64
        PHASE(64, { ew0_task(P, ti); })
        // P4: gi1 = h0p @ w_ih1^T  x192
        PHASE(192, {
            gemm_task<1,0>(&sm, ti*8, P.h0p, nullptr, 512, P.w_ih1, P.b_ih1, P.gi1, 1536, 0, nullptr);
        })
        // P5: GRU1 elementwise + comb store  x64
        PHASE(64, { ew1_task(P, ti, t, ctxr_cur); })
    }
}

// ---------------- driver -------------------------------------------------------
extern "C" void kernel_launch(void* const* d_in, const int* in_sizes, int n_in,
                              void* d_out, int out_size){
    const int*   tgt   = (const int*)  d_in[0];
    const float* enc   = (const float*)d_in[1];
    const float* dec   = (const float*)d_in[2];
    const int*   mask  = (const int*)  d_in[3];
    const float* embt  = (const float*)d_in[4];
    const float* w_ep  = (const float*)d_in[5];
    const float* b_ep  = (const float*)d_in[6];
    const float* wq    = (const float*)d_in[7];
    const float* bq    = (const float*)d_in[8];
    const float* wk    = (const float*)d_in[9];
    const float* bk    = (const float*)d_in[10];
    const float* wv    = (const float*)d_in[11];
    const float* bv    = (const float*)d_in[12];
    const float* wo    = (const float*)d_in[13];
    const float* bo    = (const float*)d_in[14];
    const float* w_ih0 = (const float*)d_in[15];
    const float* w_hh0 = (const float*)d_in[16];
    const float* b_ih0 = (const float*)d_in[17];
    const float* b_hh0 = (const float*)d_in[18];
    const float* w_ih1 = (const float*)d_in[19];
    const float* w_hh1 = (const float*)d_in[20];
    const float* b_ih1 = (const float*)d_in[21];
    const float* b_hh1 = (const float*)d_in[22];
    const float* w_o1  = (const float*)d_in[23];
    const float* b_o1  = (const float*)d_in[24];
    const float* w_o2  = (const float*)d_in[25];
    const float* b_o2  = (const float*)d_in[26];
    float* out = (float*)d_out;

    float* buf = nullptr;
    cudaGetSymbolAddress((void**)&buf, g_buf);

    Params P;
    P.tgt = tgt; P.mask = mask;
    P.embt = embt; P.w_ep = w_ep; P.b_ep = b_ep;
    P.wq = wq; P.bq = bq; P.wo = wo; P.bo = bo;
    P.w_ih0 = w_ih0; P.w_hh0 = w_hh0; P.b_ih0 = b_ih0; P.b_hh0 = b_hh0;
    P.w_ih1 = w_ih1; P.w_hh1 = w_hh1; P.b_ih1 = b_ih1; P.b_hh1 = b_hh1;
    P.Kh = buf + O_KH; P.Vh = buf + O_VH;
    P.h0 = buf + O_H0; P.h1 = buf + O_H1; P.h0p = buf + O_H0P;
    P.emb = buf + O_EMB; P.ctxr = buf + O_CTXR;
    P.gh0 = buf + O_GH0; P.gh1 = buf + O_GH1;
    P.gi0 = buf + O_GI0; P.gi1 = buf + O_GI1;
    P.comb = buf + O_COMB;
    float* o1 = buf + O_O1;

    reset_kernel<<<1, 32>>>();
    init_kernel<<<(Bb*Hh+255)/256, 256>>>(dec, bo, P.h0, P.h1, P.ctxr);
    zero_kernel<<<(Bb*Vv+255)/256, 256>>>(out);

    // step-invariant K/V projections (Kh clipped, Vh plain)
    gemm128_kernel<<<dim3(Hh/128, (Bb*Ss)/128), 256>>>(enc, wk, bk, (float*)P.Kh, Bb*Ss, Hh, Hh, 1);
    gemm128_kernel<<<dim3(Hh/128, (Bb*Ss)/128), 256>>>(enc, wv, bv, (float*)P.Vh, Bb*Ss, Hh, Hh, 0);

    // full 63-step recurrence in one persistent kernel
    decoder_loop_kernel<<<NBLK2, 256>>>(P);

    // batched output MLP over all 63 steps
    gemm128_kernel<<<dim3(Hh/128, (STEPS*Bb+127)/128), 256>>>(
        P.comb, w_o1, b_o1, o1, STEPS*Bb, Hh, 2*Hh, 2);           // relu
    gemm128_kernel<<<dim3(Vv/128, (STEPS*Bb+127)/128), 256>>>(
        o1, w_o2, b_o2, out, STEPS*Bb, Vv, Hh, 3);                // clip + scatter
}